// round 15
// baseline (speedup 1.0000x reference)
#include <cuda_runtime.h>
#include <cuda_bf16.h>
#include <math_constants.h>

// SINGLE fused kernel: bin (radar 16^3 / queries 8^3, spread over all 512
// blocks) -> software grid barrier (volatile-load polling, NOT atomic
// polling: L2 atomic ALU serializes per-address at ~32cyc/op, so 511
// atomic pollers delayed the release by ~8us in R13/R14) -> per-cell query
// (R11 structure) -> last-block cleanup (re-zeroes counters + barrier words,
// maintaining the all-zero entry invariant across graph replays).
// Grid barrier safe: __launch_bounds__(256,4) => 4 blocks/SM co-resident,
// 148*4=592 >= 512 blocks, all blocks run concurrently.
//
// Query phase: block per 8^3 cell stages the 6x6x6 patch of 16^3 buckets
// inner-first (inner 4x4x4 covers block +- 6.25, ~78 pts); main loop
// (2 thr/query) scans inner only. Unscanned points have true dist^2 >
// 39.0625 => best < 38.0 (>=1.0 rounding slack) is final. Non-final queries:
// warp-autonomous epilogue scans the whole staged patch (unstaged > 156.25
// -> bound 155.25), else full scan. Any bucket overflow -> full-scan path.
// All reductions: u64 min over (ordered-dist | orig idx) — order-invariant,
// ties -> smallest original index == jnp.argmin first occurrence.
// Distance arithmetic bit-identical to the reference:
//   l2/r2 : round(x*x)+round(y*y)+round(z*z), rounded adds (NO fma)
//   cross : fma chain (K=3 GEMM style);  dist : fmaf(-2,c, round(l2+r2))

#define RGDIM  16
#define RNCELL (RGDIM * RGDIM * RGDIM)     // 4096
#define RCELLW 6.25f
#define QGDIM  8
#define QNCELL (QGDIM * QGDIM * QGDIM)     // 512
#define QCELLW 12.5f
#define MAXNPT 8192
#define MAXV   65536
#define CAP_R  16
#define CAP_Q  224
#define SCAP   528
#define NPATCH 216                         // 6x6x6
#define QBLK   256

#define T1_KEY 0xC2180000u   /* ordered(38.0f)   */
#define T2_KEY 0xC31B4000u   /* ordered(155.25f) */

__device__ int    g_counts[RNCELL + QNCELL];   // zero at entry (invariant)
__device__ int    g_bar, g_rel, g_done;        // barrier + cleanup ticket
__device__ float4 g_pts[MAXNPT];               // raw order {x,y,z,r2}
__device__ float  g_sal[MAXNPT];
__device__ float4 g_rbucket[RNCELL * CAP_R];
__device__ int    g_rbidx[RNCELL * CAP_R];
__device__ int    g_qbucket[QNCELL * CAP_Q];
__device__ int    g_qcell[MAXV];

__device__ __forceinline__ float sum_sq_ref(float x, float y, float z) {
    float x2 = __fmul_rn(x, x);
    float y2 = __fmul_rn(y, y);
    float z2 = __fmul_rn(z, z);
    return __fadd_rn(__fadd_rn(x2, y2), z2);
}

__device__ __forceinline__ int ccoord16(float x) {
    int c = (int)(x * (1.0f / RCELLW));
    return min(max(c, 0), RGDIM - 1);
}
__device__ __forceinline__ int ccoord8(float x) {
    int c = (int)(x * (1.0f / QCELLW));
    return min(max(c, 0), QGDIM - 1);
}

__device__ __forceinline__ unsigned float_ordered(float f) {
    unsigned u = __float_as_uint(f);
    return (u & 0x80000000u) ? ~u : (u | 0x80000000u);
}

__device__ __forceinline__ unsigned long long dist_key(
    float x, float y, float z, float l2, float4 pt, int idx) {
    float c = fmaf(z, pt.z, fmaf(y, pt.y, __fmul_rn(x, pt.x)));
    float d = fmaf(-2.0f, c, __fadd_rn(l2, pt.w));
    return ((unsigned long long)float_ordered(d) << 32) | (unsigned)idx;
}

__device__ __forceinline__ int warp_incl_scan(int v, int lane) {
    #pragma unroll
    for (int s = 1; s < 32; s <<= 1) {
        int u = __shfl_up_sync(0xffffffffu, v, s);
        if (lane >= s) v += u;
    }
    return v;
}

// n1(c) = #{u < c : u in [1,4]}
__device__ __forceinline__ int n1f(int c) { return min(max(c - 1, 0), 4); }

__global__ void __launch_bounds__(QBLK, 4) fused_kernel(
    const float* __restrict__ feat,
    const float* __restrict__ rcoords,
    const float* __restrict__ lcoords,
    float* __restrict__ out, int N, int V) {
    __shared__ float4 s_pts[SCAP];
    __shared__ int    s_idx[SCAP];
    __shared__ int    s_cnt[QBLK];
    __shared__ int    s_off[QBLK];
    __shared__ int    s_cid[NPATCH];
    __shared__ int    s_wsum[8];
    __shared__ int    s_wbase[8];
    __shared__ int    s_innerTot, s_total, s_ln, s_last;
    __shared__ int    s_lv[CAP_Q];
    __shared__ unsigned long long s_lk[CAP_Q];

    const int tid  = threadIdx.x;
    const int wid  = tid >> 5;
    const int lane = tid & 31;

    // ===== Phase 1: binning, ~108 contiguous points per block =============
    {
        const int NV    = N + V;
        const int chunk = (NV + (int)gridDim.x - 1) / (int)gridDim.x;
        const int base  = blockIdx.x * chunk;
        const int end   = min(base + chunk, NV);
        for (int t = base + tid; t < end; t += QBLK) {
            if (t < N) {
                int n = t;
                float rx = rcoords[3 * n + 0];
                float ry = rcoords[3 * n + 1];
                float rz = rcoords[3 * n + 2];
                float4 p = make_float4(rx, ry, rz, sum_sq_ref(rx, ry, rz));
                g_pts[n] = p;
                float f0 = feat[64 * n + 0];
                float f1 = feat[64 * n + 1];
                float s = __fadd_rn(__fmul_rn(0.6f, fabsf(f0)), __fmul_rn(0.4f, f1));
                g_sal[n] = 1.0f / (1.0f + expf(-s));
                int c = (ccoord16(rz) * RGDIM + ccoord16(ry)) * RGDIM + ccoord16(rx);
                int pos = atomicAdd(&g_counts[c], 1);
                if (pos < CAP_R) {
                    g_rbucket[c * CAP_R + pos] = p;
                    g_rbidx[c * CAP_R + pos] = n;
                }
            } else {
                int v = t - N;
                float x = lcoords[3 * v + 0];
                float y = lcoords[3 * v + 1];
                float z = lcoords[3 * v + 2];
                int c = (ccoord8(z) * QGDIM + ccoord8(y)) * QGDIM + ccoord8(x);
                g_qcell[v] = c;
                int pos = atomicAdd(&g_counts[RNCELL + c], 1);
                if (pos < CAP_Q) g_qbucket[c * CAP_Q + pos] = v;
            }
        }
    }

    // ===== Grid barrier: atomic arrival, VOLATILE-LOAD polling ============
    __syncthreads();
    if (tid == 0) {
        __threadfence();
        int a = atomicAdd(&g_bar, 1);
        if (a == (int)gridDim.x - 1) {
            atomicExch(&g_rel, 1);           // release (one atomic, no queue)
        } else {
            volatile int* relp = (volatile int*)&g_rel;
            while (*relp == 0) __nanosleep(64);   // plain L2 loads: no
        }                                         // per-address atomic serial.
        __threadfence();
    }
    __syncthreads();

    // ===== Phase 2: query =================================================
    const int cell = blockIdx.x;
    const int qcnt = g_counts[RNCELL + cell];
    if (qcnt > 0) {
        const int bz = cell >> 6, by = (cell >> 3) & 7, bx = cell & 7;

        // ---- Per-cell rank, id, count (inner 4x4x4 gets ranks 0..63) ----
        int rawcnt = 0;
        if (tid < NPATCH) {
            int ox = tid % 6, oy = (tid / 6) % 6, oz = tid / 36;
            int ax = 2 * bx - 2 + ox, ay = 2 * by - 2 + oy, az = 2 * bz - 2 + oz;
            bool inX = (ox >= 1 && ox <= 4), inY = (oy >= 1 && oy <= 4),
                 inZ = (oz >= 1 && oz <= 4);
            int innerBefore = n1f(oz) * 16 + (inZ ? (n1f(oy) * 4 + (inY ? n1f(ox) : 0)) : 0);
            int rank = (inX && inY && inZ) ? innerBefore : 64 + (tid - innerBefore);
            int cid = -1;
            if ((unsigned)ax < RGDIM && (unsigned)ay < RGDIM && (unsigned)az < RGDIM) {
                cid = (az * RGDIM + ay) * RGDIM + ax;
                rawcnt = g_counts[cid];
            }
            s_cid[rank] = cid;
            s_cnt[rank] = min(rawcnt, CAP_R);
        } else {
            s_cnt[tid] = 0;
        }
        if (tid == 0) s_ln = 0;
        const int r_ovf = __syncthreads_or(rawcnt > CAP_R);

        // ---- Hierarchical scan: warp shfl scans + warp-0 combine ----
        const int myc  = s_cnt[tid];
        const int incl = warp_incl_scan(myc, lane);
        if (lane == 31) s_wsum[wid] = incl;
        __syncthreads();
        if (wid == 0 && lane < 8) {
            int w = s_wsum[lane];
            int e = w;
            #pragma unroll
            for (int s = 1; s < 8; s <<= 1) {
                int u = __shfl_up_sync(0xffu, e, s);
                if (lane >= s) e += u;
            }
            e -= w;                       // exclusive base of warp `lane`
            s_wbase[lane] = e;
            if (lane == 2) s_innerTot = e;        // ranks 0..63 = warps 0,1
            if (lane == 7) s_total    = e + w;
        }
        __syncthreads();
        s_off[tid] = s_wbase[wid] + incl - myc;

        const int  total    = s_total;
        const int  innerTot = s_innerTot;
        const bool big_ovf  = r_ovf || (total > SCAP - 8);
        __syncthreads();

        // ---- Slot-parallel staging (full MLP) ----
        if (!big_ovf) {
            for (int slot = tid; slot < NPATCH * CAP_R; slot += QBLK) {
                int ci = slot >> 4, i = slot & (CAP_R - 1);
                if (i < s_cnt[ci]) {
                    int c = s_cid[ci];
                    int d = s_off[ci] + i;
                    s_pts[d] = g_rbucket[c * CAP_R + i];
                    s_idx[d] = g_rbidx[c * CAP_R + i];
                }
            }
            int paddedTotal = (total + 7) & ~7;
            if (tid < paddedTotal - total) {
                s_pts[total + tid] = make_float4(0.f, 0.f, 0.f, CUDART_INF_F);
                s_idx[total + tid] = 0;
            }
        }
        __syncthreads();

        const int paddedTotal = (total + 7) & ~7;
        const int t1end = min((innerTot + 7) & ~7, paddedTotal);

        // ---- Main loop: 2 threads/query, inner region only ----
        const bool q_ovf = (qcnt > CAP_Q);
        if (!q_ovf) {
            const int      half  = tid & 1;
            const unsigned pmask = 3u << (lane & 30);
            for (int q = (tid >> 1); q < qcnt; q += (QBLK >> 1)) {
                const int v = g_qbucket[cell * CAP_Q + q];
                const float x = lcoords[3 * v + 0];
                const float y = lcoords[3 * v + 1];
                const float z = lcoords[3 * v + 2];
                const float l2 = sum_sq_ref(x, y, z);

                unsigned long long best = ~0ull;
                if (!big_ovf) {
                    unsigned long long b0 = ~0ull, b1 = ~0ull, b2 = ~0ull, b3 = ~0ull;
                    for (int j = half * 4; j < t1end; j += 8) {
                        b0 = min(b0, dist_key(x, y, z, l2, s_pts[j + 0], s_idx[j + 0]));
                        b1 = min(b1, dist_key(x, y, z, l2, s_pts[j + 1], s_idx[j + 1]));
                        b2 = min(b2, dist_key(x, y, z, l2, s_pts[j + 2], s_idx[j + 2]));
                        b3 = min(b3, dist_key(x, y, z, l2, s_pts[j + 3], s_idx[j + 3]));
                    }
                    best = min(min(b0, b1), min(b2, b3));
                    best = min(best, __shfl_xor_sync(pmask, best, 1));
                }

                if (big_ovf || (unsigned)(best >> 32) >= T1_KEY) {
                    if (half == 0) {
                        int k = atomicAdd(&s_ln, 1);    // k < qcnt <= CAP_Q
                        s_lv[k] = v;
                        s_lk[k] = best;
                    }
                } else if (half == 0) {
                    out[v] = g_sal[(unsigned)best];
                }
            }
        }
        __syncthreads();

        // ---- Warp-autonomous epilogue for listed queries ----
        const int ln = s_ln;
        for (int k = wid; k < ln; k += QBLK / 32) {
            const int v = s_lv[k];
            const float x = lcoords[3 * v + 0];
            const float y = lcoords[3 * v + 1];
            const float z = lcoords[3 * v + 2];
            const float l2 = sum_sq_ref(x, y, z);
            unsigned long long best = s_lk[k];

            if (!big_ovf) {
                unsigned long long mine = ~0ull;
                for (int j = lane; j < total; j += 32)
                    mine = min(mine, dist_key(x, y, z, l2, s_pts[j], s_idx[j]));
                #pragma unroll
                for (int s = 16; s; s >>= 1)
                    mine = min(mine, __shfl_xor_sync(0xffffffffu, mine, s));
                best = min(best, mine);
            }
            if (big_ovf || (unsigned)(best >> 32) >= T2_KEY) {
                unsigned long long mine = ~0ull;
                for (int p = lane; p < N; p += 32)
                    mine = min(mine, dist_key(x, y, z, l2, g_pts[p], p));
                #pragma unroll
                for (int s = 16; s; s >>= 1)
                    mine = min(mine, __shfl_xor_sync(0xffffffffu, mine, s));
                best = min(best, mine);
            }
            if (lane == 0) out[v] = g_sal[(unsigned)best];
        }

        // ---- Astronomically rare: query-bucket overflow ----
        if (q_ovf) {
            for (int v = wid; v < V; v += QBLK / 32) {
                if (g_qcell[v] != cell) continue;
                const float x = lcoords[3 * v + 0];
                const float y = lcoords[3 * v + 1];
                const float z = lcoords[3 * v + 2];
                const float l2 = sum_sq_ref(x, y, z);
                unsigned long long mine = ~0ull;
                for (int p = lane; p < N; p += 32)
                    mine = min(mine, dist_key(x, y, z, l2, g_pts[p], p));
                #pragma unroll
                for (int s = 16; s; s >>= 1)
                    mine = min(mine, __shfl_xor_sync(0xffffffffu, mine, s));
                if (lane == 0) out[v] = g_sal[(unsigned)mine];
            }
        }
    }

    // ===== Cleanup: last block restores the zero invariant ================
    __syncthreads();
    if (tid == 0) {
        __threadfence();
        s_last = (atomicAdd(&g_done, 1) == (int)gridDim.x - 1);
    }
    __syncthreads();
    if (s_last) {
        for (int i = tid; i < RNCELL + QNCELL; i += QBLK)
            g_counts[i] = 0;
        __syncthreads();
        if (tid == 0) {
            g_bar = 0; g_rel = 0; g_done = 0;
            __threadfence();
        }
    }
}

extern "C" void kernel_launch(void* const* d_in, const int* in_sizes, int n_in,
                              void* d_out, int out_size) {
    const float* feat    = (const float*)d_in[0];   // [N, 64]
    const float* lcoords = (const float*)d_in[1];   // [V, 3]
    const float* rcoords = (const float*)d_in[2];   // [N, 3]
    float* out = (float*)d_out;                     // [V]

    int N = in_sizes[0] / 64;
    int V = in_sizes[1] / 3;

    fused_kernel<<<QNCELL, QBLK>>>(feat, rcoords, lcoords, out, N, V);
}

// round 16
// speedup vs baseline: 1.0102x; 1.0102x over previous
#include <cuda_runtime.h>
#include <cuda_bf16.h>
#include <math_constants.h>

// SINGLE fused kernel: bin (radar 16^3 / queries 8^3, spread over all 512
// blocks) -> software grid barrier (volatile-load polling) -> per-cell query
// (R11 structure) -> last-block cleanup (re-zeroes counters + barrier words,
// maintaining the all-zero entry invariant across graph replays).
// __launch_bounds__(256, 6): caps regs at 42 so 6 blocks/SM are resident
// (48 warps/SM) — R13-R15 compiled at 64 regs -> only 4 blocks/SM (32 warps),
// leaving ~9us of memory latency exposed (issue was 20%). Grid barrier still
// safe: 6*148 = 888 >= 512, all blocks co-resident.
//
// Query phase: block per 8^3 cell stages the 6x6x6 patch of 16^3 buckets
// inner-first (inner 4x4x4 covers block +- 6.25, ~78 pts); main loop
// (2 thr/query) scans inner only. Unscanned points have true dist^2 >
// 39.0625 => best < 38.0 (>=1.0 rounding slack) is final. Non-final queries:
// warp-autonomous epilogue scans the whole staged patch (unstaged > 156.25
// -> bound 155.25), else full scan. Any bucket overflow -> full-scan path.
// All reductions: u64 min over (ordered-dist | orig idx) — order-invariant,
// ties -> smallest original index == jnp.argmin first occurrence.
// Distance arithmetic bit-identical to the reference:
//   l2/r2 : round(x*x)+round(y*y)+round(z*z), rounded adds (NO fma)
//   cross : fma chain (K=3 GEMM style);  dist : fmaf(-2,c, round(l2+r2))

#define RGDIM  16
#define RNCELL (RGDIM * RGDIM * RGDIM)     // 4096
#define RCELLW 6.25f
#define QGDIM  8
#define QNCELL (QGDIM * QGDIM * QGDIM)     // 512
#define QCELLW 12.5f
#define MAXNPT 8192
#define MAXV   65536
#define CAP_R  16
#define CAP_Q  224
#define SCAP   528
#define NPATCH 216                         // 6x6x6
#define QBLK   256

#define T1_KEY 0xC2180000u   /* ordered(38.0f)   */
#define T2_KEY 0xC31B4000u   /* ordered(155.25f) */

__device__ int    g_counts[RNCELL + QNCELL];   // zero at entry (invariant)
__device__ int    g_bar, g_rel, g_done;        // barrier + cleanup ticket
__device__ float4 g_pts[MAXNPT];               // raw order {x,y,z,r2}
__device__ float  g_sal[MAXNPT];
__device__ float4 g_rbucket[RNCELL * CAP_R];
__device__ int    g_rbidx[RNCELL * CAP_R];
__device__ int    g_qbucket[QNCELL * CAP_Q];
__device__ int    g_qcell[MAXV];

__device__ __forceinline__ float sum_sq_ref(float x, float y, float z) {
    float x2 = __fmul_rn(x, x);
    float y2 = __fmul_rn(y, y);
    float z2 = __fmul_rn(z, z);
    return __fadd_rn(__fadd_rn(x2, y2), z2);
}

__device__ __forceinline__ int ccoord16(float x) {
    int c = (int)(x * (1.0f / RCELLW));
    return min(max(c, 0), RGDIM - 1);
}
__device__ __forceinline__ int ccoord8(float x) {
    int c = (int)(x * (1.0f / QCELLW));
    return min(max(c, 0), QGDIM - 1);
}

__device__ __forceinline__ unsigned float_ordered(float f) {
    unsigned u = __float_as_uint(f);
    return (u & 0x80000000u) ? ~u : (u | 0x80000000u);
}

__device__ __forceinline__ unsigned long long dist_key(
    float x, float y, float z, float l2, float4 pt, int idx) {
    float c = fmaf(z, pt.z, fmaf(y, pt.y, __fmul_rn(x, pt.x)));
    float d = fmaf(-2.0f, c, __fadd_rn(l2, pt.w));
    return ((unsigned long long)float_ordered(d) << 32) | (unsigned)idx;
}

__device__ __forceinline__ int warp_incl_scan(int v, int lane) {
    #pragma unroll
    for (int s = 1; s < 32; s <<= 1) {
        int u = __shfl_up_sync(0xffffffffu, v, s);
        if (lane >= s) v += u;
    }
    return v;
}

// n1(c) = #{u < c : u in [1,4]}
__device__ __forceinline__ int n1f(int c) { return min(max(c - 1, 0), 4); }

__global__ void __launch_bounds__(QBLK, 6) fused_kernel(
    const float* __restrict__ feat,
    const float* __restrict__ rcoords,
    const float* __restrict__ lcoords,
    float* __restrict__ out, int N, int V) {
    __shared__ float4 s_pts[SCAP];
    __shared__ int    s_idx[SCAP];
    __shared__ int    s_cnt[QBLK];
    __shared__ int    s_off[QBLK];
    __shared__ int    s_cid[NPATCH];
    __shared__ int    s_wsum[8];
    __shared__ int    s_wbase[8];
    __shared__ int    s_innerTot, s_total, s_ln, s_last;
    __shared__ int    s_lv[CAP_Q];
    __shared__ unsigned long long s_lk[CAP_Q];

    const int tid  = threadIdx.x;
    const int wid  = tid >> 5;
    const int lane = tid & 31;

    // ===== Phase 1: binning, ~108 contiguous points per block =============
    {
        const int NV    = N + V;
        const int chunk = (NV + (int)gridDim.x - 1) / (int)gridDim.x;
        const int base  = blockIdx.x * chunk;
        const int end   = min(base + chunk, NV);
        for (int t = base + tid; t < end; t += QBLK) {
            if (t < N) {
                int n = t;
                float rx = rcoords[3 * n + 0];
                float ry = rcoords[3 * n + 1];
                float rz = rcoords[3 * n + 2];
                float4 p = make_float4(rx, ry, rz, sum_sq_ref(rx, ry, rz));
                g_pts[n] = p;
                float f0 = feat[64 * n + 0];
                float f1 = feat[64 * n + 1];
                float s = __fadd_rn(__fmul_rn(0.6f, fabsf(f0)), __fmul_rn(0.4f, f1));
                g_sal[n] = 1.0f / (1.0f + expf(-s));
                int c = (ccoord16(rz) * RGDIM + ccoord16(ry)) * RGDIM + ccoord16(rx);
                int pos = atomicAdd(&g_counts[c], 1);
                if (pos < CAP_R) {
                    g_rbucket[c * CAP_R + pos] = p;
                    g_rbidx[c * CAP_R + pos] = n;
                }
            } else {
                int v = t - N;
                float x = lcoords[3 * v + 0];
                float y = lcoords[3 * v + 1];
                float z = lcoords[3 * v + 2];
                int c = (ccoord8(z) * QGDIM + ccoord8(y)) * QGDIM + ccoord8(x);
                g_qcell[v] = c;
                int pos = atomicAdd(&g_counts[RNCELL + c], 1);
                if (pos < CAP_Q) g_qbucket[c * CAP_Q + pos] = v;
            }
        }
    }

    // ===== Grid barrier: atomic arrival, volatile-load polling ============
    __syncthreads();
    if (tid == 0) {
        __threadfence();
        int a = atomicAdd(&g_bar, 1);
        if (a == (int)gridDim.x - 1) {
            atomicExch(&g_rel, 1);
        } else {
            volatile int* relp = (volatile int*)&g_rel;
            while (*relp == 0) __nanosleep(64);
        }
        __threadfence();
    }
    __syncthreads();

    // ===== Phase 2: query =================================================
    const int cell = blockIdx.x;
    const int qcnt = g_counts[RNCELL + cell];
    if (qcnt > 0) {
        const int bz = cell >> 6, by = (cell >> 3) & 7, bx = cell & 7;

        // ---- Per-cell rank, id, count (inner 4x4x4 gets ranks 0..63) ----
        int rawcnt = 0;
        if (tid < NPATCH) {
            int ox = tid % 6, oy = (tid / 6) % 6, oz = tid / 36;
            int ax = 2 * bx - 2 + ox, ay = 2 * by - 2 + oy, az = 2 * bz - 2 + oz;
            bool inX = (ox >= 1 && ox <= 4), inY = (oy >= 1 && oy <= 4),
                 inZ = (oz >= 1 && oz <= 4);
            int innerBefore = n1f(oz) * 16 + (inZ ? (n1f(oy) * 4 + (inY ? n1f(ox) : 0)) : 0);
            int rank = (inX && inY && inZ) ? innerBefore : 64 + (tid - innerBefore);
            int cid = -1;
            if ((unsigned)ax < RGDIM && (unsigned)ay < RGDIM && (unsigned)az < RGDIM) {
                cid = (az * RGDIM + ay) * RGDIM + ax;
                rawcnt = g_counts[cid];
            }
            s_cid[rank] = cid;
            s_cnt[rank] = min(rawcnt, CAP_R);
        } else {
            s_cnt[tid] = 0;
        }
        if (tid == 0) s_ln = 0;
        const int r_ovf = __syncthreads_or(rawcnt > CAP_R);

        // ---- Hierarchical scan: warp shfl scans + warp-0 combine ----
        const int myc  = s_cnt[tid];
        const int incl = warp_incl_scan(myc, lane);
        if (lane == 31) s_wsum[wid] = incl;
        __syncthreads();
        if (wid == 0 && lane < 8) {
            int w = s_wsum[lane];
            int e = w;
            #pragma unroll
            for (int s = 1; s < 8; s <<= 1) {
                int u = __shfl_up_sync(0xffu, e, s);
                if (lane >= s) e += u;
            }
            e -= w;                       // exclusive base of warp `lane`
            s_wbase[lane] = e;
            if (lane == 2) s_innerTot = e;        // ranks 0..63 = warps 0,1
            if (lane == 7) s_total    = e + w;
        }
        __syncthreads();
        s_off[tid] = s_wbase[wid] + incl - myc;

        const int  total    = s_total;
        const int  innerTot = s_innerTot;
        const bool big_ovf  = r_ovf || (total > SCAP - 8);
        __syncthreads();

        // ---- Slot-parallel staging (full MLP) ----
        if (!big_ovf) {
            for (int slot = tid; slot < NPATCH * CAP_R; slot += QBLK) {
                int ci = slot >> 4, i = slot & (CAP_R - 1);
                if (i < s_cnt[ci]) {
                    int c = s_cid[ci];
                    int d = s_off[ci] + i;
                    s_pts[d] = g_rbucket[c * CAP_R + i];
                    s_idx[d] = g_rbidx[c * CAP_R + i];
                }
            }
            int paddedTotal = (total + 7) & ~7;
            if (tid < paddedTotal - total) {
                s_pts[total + tid] = make_float4(0.f, 0.f, 0.f, CUDART_INF_F);
                s_idx[total + tid] = 0;
            }
        }
        __syncthreads();

        const int paddedTotal = (total + 7) & ~7;
        const int t1end = min((innerTot + 7) & ~7, paddedTotal);

        // ---- Main loop: 2 threads/query, inner region only ----
        const bool q_ovf = (qcnt > CAP_Q);
        if (!q_ovf) {
            const int      half  = tid & 1;
            const unsigned pmask = 3u << (lane & 30);
            for (int q = (tid >> 1); q < qcnt; q += (QBLK >> 1)) {
                const int v = g_qbucket[cell * CAP_Q + q];
                const float x = lcoords[3 * v + 0];
                const float y = lcoords[3 * v + 1];
                const float z = lcoords[3 * v + 2];
                const float l2 = sum_sq_ref(x, y, z);

                unsigned long long best = ~0ull;
                if (!big_ovf) {
                    unsigned long long b0 = ~0ull, b1 = ~0ull, b2 = ~0ull, b3 = ~0ull;
                    for (int j = half * 4; j < t1end; j += 8) {
                        b0 = min(b0, dist_key(x, y, z, l2, s_pts[j + 0], s_idx[j + 0]));
                        b1 = min(b1, dist_key(x, y, z, l2, s_pts[j + 1], s_idx[j + 1]));
                        b2 = min(b2, dist_key(x, y, z, l2, s_pts[j + 2], s_idx[j + 2]));
                        b3 = min(b3, dist_key(x, y, z, l2, s_pts[j + 3], s_idx[j + 3]));
                    }
                    best = min(min(b0, b1), min(b2, b3));
                    best = min(best, __shfl_xor_sync(pmask, best, 1));
                }

                if (big_ovf || (unsigned)(best >> 32) >= T1_KEY) {
                    if (half == 0) {
                        int k = atomicAdd(&s_ln, 1);    // k < qcnt <= CAP_Q
                        s_lv[k] = v;
                        s_lk[k] = best;
                    }
                } else if (half == 0) {
                    out[v] = g_sal[(unsigned)best];
                }
            }
        }
        __syncthreads();

        // ---- Warp-autonomous epilogue for listed queries ----
        const int ln = s_ln;
        for (int k = wid; k < ln; k += QBLK / 32) {
            const int v = s_lv[k];
            const float x = lcoords[3 * v + 0];
            const float y = lcoords[3 * v + 1];
            const float z = lcoords[3 * v + 2];
            const float l2 = sum_sq_ref(x, y, z);
            unsigned long long best = s_lk[k];

            if (!big_ovf) {
                unsigned long long mine = ~0ull;
                for (int j = lane; j < total; j += 32)
                    mine = min(mine, dist_key(x, y, z, l2, s_pts[j], s_idx[j]));
                #pragma unroll
                for (int s = 16; s; s >>= 1)
                    mine = min(mine, __shfl_xor_sync(0xffffffffu, mine, s));
                best = min(best, mine);
            }
            if (big_ovf || (unsigned)(best >> 32) >= T2_KEY) {
                unsigned long long mine = ~0ull;
                for (int p = lane; p < N; p += 32)
                    mine = min(mine, dist_key(x, y, z, l2, g_pts[p], p));
                #pragma unroll
                for (int s = 16; s; s >>= 1)
                    mine = min(mine, __shfl_xor_sync(0xffffffffu, mine, s));
                best = min(best, mine);
            }
            if (lane == 0) out[v] = g_sal[(unsigned)best];
        }

        // ---- Astronomically rare: query-bucket overflow ----
        if (q_ovf) {
            for (int v = wid; v < V; v += QBLK / 32) {
                if (g_qcell[v] != cell) continue;
                const float x = lcoords[3 * v + 0];
                const float y = lcoords[3 * v + 1];
                const float z = lcoords[3 * v + 2];
                const float l2 = sum_sq_ref(x, y, z);
                unsigned long long mine = ~0ull;
                for (int p = lane; p < N; p += 32)
                    mine = min(mine, dist_key(x, y, z, l2, g_pts[p], p));
                #pragma unroll
                for (int s = 16; s; s >>= 1)
                    mine = min(mine, __shfl_xor_sync(0xffffffffu, mine, s));
                if (lane == 0) out[v] = g_sal[(unsigned)mine];
            }
        }
    }

    // ===== Cleanup: last block restores the zero invariant ================
    __syncthreads();
    if (tid == 0) {
        __threadfence();
        s_last = (atomicAdd(&g_done, 1) == (int)gridDim.x - 1);
    }
    __syncthreads();
    if (s_last) {
        for (int i = tid; i < RNCELL + QNCELL; i += QBLK)
            g_counts[i] = 0;
        __syncthreads();
        if (tid == 0) {
            g_bar = 0; g_rel = 0; g_done = 0;
            __threadfence();
        }
    }
}

extern "C" void kernel_launch(void* const* d_in, const int* in_sizes, int n_in,
                              void* d_out, int out_size) {
    const float* feat    = (const float*)d_in[0];   // [N, 64]
    const float* lcoords = (const float*)d_in[1];   // [V, 3]
    const float* rcoords = (const float*)d_in[2];   // [N, 3]
    float* out = (float*)d_out;                     // [V]

    int N = in_sizes[0] / 64;
    int V = in_sizes[1] / 3;

    fused_kernel<<<QNCELL, QBLK>>>(feat, rcoords, lcoords, out, N, V);
}